// round 1
// baseline (speedup 1.0000x reference)
#include <cuda_runtime.h>

// gcc_Conv2d_64347200028713: circular depthwise conv along H (kernel = full H),
// B=32, C=384, H=W=56, fp32.
// out[b,c,h,w] = bias[c] + sum_k weight[c,k] * x[b,c,(h+k)%56,w]
//
// One block per (b,c) plane. Plane staged in smem. Each thread owns one
// f32x2 column pair and 7 consecutive output rows, using a 7-deep sliding
// register window so each k-step costs 1 LDS.64 + 7 fma.rn.f32x2 (FFMA2).

#define HB 56
#define WB 56
#define CCH 384
#define PLANE (HB * WB)          // 3136
#define NWPAIR (WB / 2)          // 28
#define HGROUP 7                 // rows per thread
#define NTHREADS (NWPAIR * (HB / HGROUP))  // 28 * 8 = 224

typedef unsigned long long ull;

__device__ __forceinline__ ull pack2(float lo, float hi) {
    ull r;
    asm("mov.b64 %0, {%1, %2};" : "=l"(r) : "f"(lo), "f"(hi));
    return r;
}

__device__ __forceinline__ void ffma2(ull& d, ull a, ull b, ull c) {
    asm("fma.rn.f32x2 %0, %1, %2, %3;" : "=l"(d) : "l"(a), "l"(b), "l"(c));
}

__global__ __launch_bounds__(NTHREADS)
void gcc_conv_circ_kernel(const float* __restrict__ x,
                          const float* __restrict__ weight,
                          const float* __restrict__ bias,
                          float* __restrict__ out) {
    __shared__ float s_x[PLANE];   // 12544 B
    __shared__ float s_w[HB];
    __shared__ float s_b;

    const int plane = blockIdx.x;          // b*C + c
    const int c = plane % CCH;
    const float* __restrict__ xp = x + (size_t)plane * PLANE;
    float* __restrict__ op = out + (size_t)plane * PLANE;
    const int tid = threadIdx.x;

    // Cooperative plane load: 784 float4 across 224 threads (3.5 each)
    const float4* __restrict__ xp4 = (const float4*)xp;
    float4* s_x4 = (float4*)s_x;
#pragma unroll
    for (int i = tid; i < PLANE / 4; i += NTHREADS) s_x4[i] = xp4[i];
    if (tid < HB) s_w[tid] = weight[c * HB + tid];
    if (tid == 0) s_b = bias[c];
    __syncthreads();

    const int wp = tid % NWPAIR;             // column pair 0..27
    const int h0 = (tid / NWPAIR) * HGROUP;  // 0,7,...,49

    const float bv = s_b;
    const ull bias2 = pack2(bv, bv);
    ull acc[HGROUP];
#pragma unroll
    for (int i = 0; i < HGROUP; i++) acc[i] = bias2;

    // Window prologue: win[i] = x row (h0+i) at this thread's column pair.
    // h0+i <= 55, no wrap needed.
    ull win[HGROUP];
#pragma unroll
    for (int i = 0; i < HGROUP; i++) {
        win[i] = *(const ull*)&s_x[(h0 + i) * WB + 2 * wp];
    }

    // Main loop: at step k, acc[i] needs row (h0+i+k)%56 == win[(k+i)%7].
#pragma unroll
    for (int k = 0; k < HB; k++) {
        const float wk = s_w[k];             // uniform -> LDS broadcast
        const ull wk2 = pack2(wk, wk);
#pragma unroll
        for (int i = 0; i < HGROUP; i++) {
            ffma2(acc[i], wk2, win[(k + i) % HGROUP], acc[i]);
        }
        if (k < HB - 1) {
            int r = h0 + k + HGROUP;         // next row entering the window
            if (r >= HB) r -= HB;            // max 110 -> one subtract suffices
            win[k % HGROUP] = *(const ull*)&s_x[r * WB + 2 * wp];
        }
    }

#pragma unroll
    for (int i = 0; i < HGROUP; i++) {
        *(ull*)&op[(h0 + i) * WB + 2 * wp] = acc[i];
    }
}

extern "C" void kernel_launch(void* const* d_in, const int* in_sizes, int n_in,
                              void* d_out, int out_size) {
    const float* x = (const float*)d_in[0];       // [32,384,56,56]
    const float* weight = (const float*)d_in[1];  // [384,1,56,1] -> [384,56]
    const float* bias = (const float*)d_in[2];    // [384]
    float* out = (float*)d_out;

    const int nplanes = 32 * CCH;                 // 12288
    gcc_conv_circ_kernel<<<nplanes, NTHREADS>>>(x, weight, bias, out);
}